// round 8
// baseline (speedup 1.0000x reference)
#include <cuda_runtime.h>
#include <cuda_bf16.h>
#include <math.h>

// Problem constants
#define VV    32000
#define EE    256
#define DD    25
#define BB    64
#define TT    24
#define HH    625          // D*D
#define INDIM 906          // E + H + D
#define KTOT  1556         // IN + H(hS) + D(hU)
#define KP    1600         // padded K for gate GEMM
#define NG    2600         // 4H + 4D real gate rows
#define NGP   2624         // padded to 82*32
#define NSTEPS 23
#define KFC   640          // padded 625 for final GEMM
#define NBS   82           // persistent blocks for steps (82 n32-tiles)

// ---------------- static device scratch (zero-initialized at load) ----------
__device__ unsigned short g_Wh[NGP * KP];     // gate weights bf16 hi (pad rows/cols = 0)
__device__ unsigned short g_Wl[NGP * KP];     // gate weights bf16 lo
__device__ float g_bias[NG];
__device__ unsigned short g_fcWh[VV * KFC];   // fcW bf16 hi
__device__ unsigned short g_fcWl[VV * KFC];   // fcW bf16 lo
__device__ unsigned short g_xhh[BB * KP];     // xh bf16 hi [cU|word|cS|hS|hU|pad]
__device__ unsigned short g_xhl[BB * KP];     // xh bf16 lo
__device__ float g_G[BB * NGP];               // gate pre-activations
__device__ float g_cS[BB * HH];
__device__ float g_cU[BB * DD];
__device__ unsigned short g_fth[TT * BB * KFC];  // ft bf16 hi (t=0 + pad stay 0)
__device__ unsigned short g_ftl[TT * BB * KFC];  // ft bf16 lo
__device__ unsigned int g_bar;

__device__ __forceinline__ float sigmoidf_(float x) {
    return __fdividef(1.f, 1.f + __expf(-x));
}
__device__ __forceinline__ float tanhf_(float x) {
    return 1.f - __fdividef(2.f, 1.f + __expf(2.f * x));
}

__device__ __forceinline__ unsigned short f2bf(float v) {
    __nv_bfloat16 b = __float2bfloat16(v);
    return *reinterpret_cast<unsigned short*>(&b);
}
__device__ __forceinline__ float bf2f(unsigned short u) {
    __nv_bfloat16 b;
    *reinterpret_cast<unsigned short*>(&b) = u;
    return __bfloat162float(b);
}
__device__ __forceinline__ void wr_xh(int b, int idx, float v) {
    unsigned short h = f2bf(v);
    g_xhh[b * KP + idx] = h;
    g_xhl[b * KP + idx] = f2bf(v - bf2f(h));
}

__device__ __forceinline__ void grid_sync_() {
    __syncthreads();
    if (threadIdx.x == 0) {
        __threadfence();
        unsigned int t = atomicAdd(&g_bar, 1u);
        unsigned int target = t - (t % NBS) + NBS;
        volatile unsigned int* p = &g_bar;
        while ((int)(*p - target) < 0) { }
    }
    __syncthreads();
}

__device__ __forceinline__ void cp16(void* sdst, const void* gsrc) {
    unsigned saddr = (unsigned)__cvta_generic_to_shared(sdst);
    asm volatile("cp.async.cg.shared.global [%0], [%1], 16;" :: "r"(saddr), "l"(gsrc));
}

__device__ __forceinline__ void mma_bf16(float c[4], unsigned a0, unsigned a1,
                                         unsigned a2, unsigned a3,
                                         unsigned b0, unsigned b1) {
    asm volatile(
        "mma.sync.aligned.m16n8k16.row.col.f32.bf16.bf16.f32 "
        "{%0,%1,%2,%3},{%4,%5,%6,%7},{%8,%9},{%0,%1,%2,%3};"
        : "+f"(c[0]), "+f"(c[1]), "+f"(c[2]), "+f"(c[3])
        : "r"(a0), "r"(a1), "r"(a2), "r"(a3), "r"(b0), "r"(b1));
}

__device__ __forceinline__ void ldsm4(unsigned& r0, unsigned& r1, unsigned& r2,
                                      unsigned& r3, const unsigned short* p) {
    unsigned a = (unsigned)__cvta_generic_to_shared(p);
    asm volatile("ldmatrix.sync.aligned.m8n8.x4.shared.b16 {%0,%1,%2,%3},[%4];"
                 : "=r"(r0), "=r"(r1), "=r"(r2), "=r"(r3) : "r"(a));
}
__device__ __forceinline__ void ldsm2(unsigned& r0, unsigned& r1, const unsigned short* p) {
    unsigned a = (unsigned)__cvta_generic_to_shared(p);
    asm volatile("ldmatrix.sync.aligned.m8n8.x2.shared.b16 {%0,%1},[%2];"
                 : "=r"(r0), "=r"(r1) : "r"(a));
}

// ---------------- weight packing -------------------------------------------
__global__ void pack_kernel(const float* __restrict__ WihS, const float* __restrict__ WhhS,
                            const float* __restrict__ bihS, const float* __restrict__ bhhS,
                            const float* __restrict__ WihU, const float* __restrict__ WhhU,
                            const float* __restrict__ bihU, const float* __restrict__ bhhU,
                            const float* __restrict__ fcW) {
    const long long n_wcat = (long long)NGP * KP;
    const long long n_fc   = (long long)VV * KFC;
    const long long total  = n_wcat + n_fc + NG;
    for (long long i = blockIdx.x * (long long)blockDim.x + threadIdx.x; i < total;
         i += (long long)gridDim.x * blockDim.x) {
        if (i < n_wcat) {
            int n = (int)(i / KP), k = (int)(i % KP);
            float v = 0.f;
            if (n < 4 * HH) {
                if (k < INDIM)            v = WihS[n * INDIM + k];
                else if (k < INDIM + HH)  v = WhhS[n * HH + (k - INDIM)];
            } else if (n < NG) {
                int nu = n - 4 * HH;
                if (k < INDIM)                          v = WihU[nu * INDIM + k];
                else if (k >= INDIM + HH && k < KTOT)   v = WhhU[nu * DD + (k - INDIM - HH)];
            }
            unsigned short h = f2bf(v);
            g_Wh[i] = h;
            g_Wl[i] = f2bf(v - bf2f(h));
        } else if (i < n_wcat + n_fc) {
            long long j = i - n_wcat;
            int k = (int)(j % KFC);
            int n = (int)(j / KFC);
            float v = (k < HH) ? fcW[(long long)n * HH + k] : 0.f;
            unsigned short h = f2bf(v);
            g_fcWh[j] = h;
            g_fcWl[j] = f2bf(v - bf2f(h));
        } else {
            int n = (int)(i - n_wcat - n_fc);
            g_bias[n] = (n < 4 * HH) ? (bihS[n] + bhhS[n]) : (bihU[n - 4 * HH] + bhhU[n - 4 * HH]);
        }
    }
}

// ---------------- initial state --------------------------------------------
__global__ void init_kernel(const float* __restrict__ features, const float* __restrict__ embed,
                            const float* __restrict__ szW, const float* __restrict__ szb) {
    __shared__ float sf[EE];
    const int b = blockIdx.x, tid = threadIdx.x;
    sf[tid] = features[b * EE + tid];
    __syncthreads();
    for (int c = tid; c < HH; c += 256) {
        float acc = szb[c];
        const float* w = szW + c * EE;
        #pragma unroll 8
        for (int k = 0; k < EE; k++) acc += sf[k] * w[k];
        g_cS[b * HH + c] = acc;
        wr_xh(b, 281 + c, acc);   // cS slot
        wr_xh(b, 906 + c, 0.f);   // hS = 0
    }
    if (tid < DD) {
        g_cU[b * DD + tid] = 0.f;
        wr_xh(b, tid, 0.f);          // cU = 0
        wr_xh(b, 1531 + tid, 0.f);   // hU = 0
    }
    wr_xh(b, 25 + tid, embed[tid]);  // word0
}

// ---------------- persistent recurrence ------------------------------------
// 82 blocks x 128 threads. Phase A: G = xh @ Wcat^T on tensor cores, block tile
// 64(M) x 32(N), 4 warps each owning 8 gate rows, full K=1600, smem-staged
// chunks (cp.async 3-deep) + ldmatrix. No k-split -> no reduction. Phase B:
// blocks 0..63 apply LSTM cells, rebuild xh (bf16 hi/lo), compute ft.
__global__ void __launch_bounds__(128)
steps_kernel(const int* __restrict__ captions, const float* __restrict__ embed,
             const float* __restrict__ wuW, const float* __restrict__ wub) {
    __shared__ unsigned short sAh[3][64 * 16], sAl[3][64 * 16];
    __shared__ unsigned short sBh[3][32 * 16], sBl[3][32 * 16];
    __shared__ float shS[HH];
    __shared__ float shU[DD];
    __shared__ float sut[HH];

    const int tid  = threadIdx.x;
    const int lane = tid & 31;
    const int w    = tid >> 5;       // warp = n-slice (8 rows each)
    const int g    = lane >> 2;
    const int t4   = lane & 3;
    const int n0   = blockIdx.x * 32;

    // cp.async per-thread coords
    const int arow  = tid >> 1;              // 0..63
    const int ahalf = (tid & 1) * 8;
    const int brow  = (tid & 63) >> 1;       // 0..31
    const bool isBl = (tid >= 64);

    // ldmatrix per-lane offsets (shorts), row stride 16
    const int apos = (lane & 15) * 16 + (lane >> 4) * 8;
    const int bpos = (w * 8 + (lane & 7)) * 16 + ((lane >> 3) & 1) * 8;

    for (int s = 0; s < NSTEPS; s++) {
        // ---------- phase A ----------
        float acc[4][4];
        #pragma unroll
        for (int mf = 0; mf < 4; mf++)
            #pragma unroll
            for (int r = 0; r < 4; r++) acc[mf][r] = 0.f;

        // stage loader
        #define LOAD_STAGE(st, kk) do {                                              \
            cp16(&sAh[st][arow * 16 + ahalf], g_xhh + arow * KP + (kk) + ahalf);     \
            cp16(&sAl[st][arow * 16 + ahalf], g_xhl + arow * KP + (kk) + ahalf);     \
            if (!isBl) cp16(&sBh[st][brow * 16 + ahalf],                             \
                            g_Wh + (long long)(n0 + brow) * KP + (kk) + ahalf);      \
            else       cp16(&sBl[st][brow * 16 + ahalf],                             \
                            g_Wl + (long long)(n0 + brow) * KP + (kk) + ahalf);      \
        } while (0)

        LOAD_STAGE(0, 0);
        asm volatile("cp.async.commit_group;");
        LOAD_STAGE(1, 16);
        asm volatile("cp.async.commit_group;");

        for (int it = 0; it < 100; it++) {
            asm volatile("cp.async.wait_group 1;" ::: "memory");
            __syncthreads();
            if (it + 2 < 100) {
                const int st = (it + 2) % 3;
                LOAD_STAGE(st, (it + 2) * 16);
            }
            asm volatile("cp.async.commit_group;");

            const int buf = it % 3;
            unsigned bh0, bh1, bl0, bl1;
            ldsm2(bh0, bh1, &sBh[buf][bpos]);
            ldsm2(bl0, bl1, &sBl[buf][bpos]);
            #pragma unroll
            for (int mf = 0; mf < 4; mf++) {
                unsigned ah0, ah1, ah2, ah3, al0, al1, al2, al3;
                ldsm4(ah0, ah1, ah2, ah3, &sAh[buf][mf * 256 + apos]);
                ldsm4(al0, al1, al2, al3, &sAl[buf][mf * 256 + apos]);
                mma_bf16(acc[mf], ah0, ah1, ah2, ah3, bh0, bh1);
                mma_bf16(acc[mf], ah0, ah1, ah2, ah3, bl0, bl1);
                mma_bf16(acc[mf], al0, al1, al2, al3, bh0, bh1);
            }
        }
        #undef LOAD_STAGE

        // write G (each warp owns its 8 columns; no reduction needed)
        #pragma unroll
        for (int mf = 0; mf < 4; mf++) {
            const int col = n0 + w * 8 + t4 * 2;
            const int m1 = mf * 16 + g;
            *(float2*)&g_G[(m1    ) * NGP + col] = make_float2(acc[mf][0], acc[mf][1]);
            *(float2*)&g_G[(m1 + 8) * NGP + col] = make_float2(acc[mf][2], acc[mf][3]);
        }
        grid_sync_();

        // ---------- phase B ----------
        if (blockIdx.x < BB) {
            const int b = blockIdx.x;
            const float* p = g_G + b * NGP;
            for (int e = tid; e < HH; e += 128) {
                float gi = __ldcg(p + e)        + g_bias[e];
                float gf = __ldcg(p + HH + e)   + g_bias[HH + e];
                float gg = __ldcg(p + 2*HH + e) + g_bias[2*HH + e];
                float go = __ldcg(p + 3*HH + e) + g_bias[3*HH + e];
                float c = sigmoidf_(gf) * g_cS[b * HH + e] + sigmoidf_(gi) * tanhf_(gg);
                float h = sigmoidf_(go) * tanhf_(c);
                g_cS[b * HH + e] = c;
                shS[e] = h;
                wr_xh(b, 281 + e, c);   // cS for next step
                wr_xh(b, 906 + e, h);   // hS
            }
            if (tid < DD) {
                const int e = tid, u = 4 * HH;
                float gi = __ldcg(p + u + e)      + g_bias[u + e];
                float gf = __ldcg(p + u + 25 + e) + g_bias[u + 25 + e];
                float gg = __ldcg(p + u + 50 + e) + g_bias[u + 50 + e];
                float go = __ldcg(p + u + 75 + e) + g_bias[u + 75 + e];
                float c = sigmoidf_(gf) * g_cU[b * DD + e] + sigmoidf_(gi) * tanhf_(gg);
                float h = sigmoidf_(go) * tanhf_(c);
                g_cU[b * DD + e] = c;
                shU[e] = h;
                wr_xh(b, e, c);          // cU
                wr_xh(b, 1531 + e, h);   // hU
            }
            if (s + 1 < NSTEPS) {
                const int wd = captions[b * TT + (s + 1)];
                for (int e = tid; e < EE; e += 128) wr_xh(b, 25 + e, embed[wd * EE + e]);
            }
            __syncthreads();
            for (int pp = tid; pp < HH; pp += 128) {   // ut = hU @ wuW.T + wub
                float acc2 = wub[pp];
                const float* r = wuW + pp * DD;
                #pragma unroll
                for (int d2 = 0; d2 < DD; d2++) acc2 += shU[d2] * r[d2];
                sut[pp] = acc2;
            }
            __syncthreads();
            const long long base = (long long)((s + 1) * BB + b) * KFC;
            for (int idx = tid; idx < HH; idx += 128) {  // ft = ut @ m2
                int i2 = idx / DD, j2 = idx - i2 * DD;
                float acc2 = 0.f;
                #pragma unroll
                for (int k2 = 0; k2 < DD; k2++) acc2 += sut[i2 * DD + k2] * shS[k2 * DD + j2];
                unsigned short h = f2bf(acc2);
                g_fth[base + idx] = h;
                g_ftl[base + idx] = f2bf(acc2 - bf2f(h));
            }
        }
        grid_sync_();
    }
}

// ---------------- final projection on tensor cores --------------------------
// out[m,n] = ft[m,:] . fcW[n,:] + fcb[n], bf16 hi/lo 3-term mma, ldmatrix
// loads, 3-stage cp.async pipeline (dynamic smem 72KB), grid m-fastest so 12
// consecutive blocks share one fcW n-tile (fcW streams from DRAM ~once).
#define FCSTR 24   // smem row stride in bf16
#define FCSTAGE_SH 12288   // shorts per stage (4 arrays x 128*24)
__global__ void __launch_bounds__(256, 2)
fc_kernel(const float* __restrict__ fcb, float* __restrict__ out) {
    extern __shared__ unsigned short sm[];

    const int tid   = threadIdx.x;
    const int lane  = tid & 31;
    const int wid   = tid >> 5;
    const int g     = lane >> 2;
    const int t4    = lane & 3;
    const int mbase = (wid & 1) * 64;
    const int nbase = (wid >> 1) * 32;
    const int m0    = blockIdx.x * 128;   // m fastest
    const int n0    = blockIdx.y * 128;

    const int lrow  = tid >> 1;
    const int lks   = (tid & 1) * 8;

    const int apos = (mbase + (lane & 15)) * FCSTR + (lane >> 4) * 8;
    const int bpos = (nbase + ((lane >> 4) & 1) * 8 + (lane & 7)) * FCSTR + ((lane >> 3) & 1) * 8;

    float acc[4][4][4];
    #pragma unroll
    for (int mf = 0; mf < 4; mf++)
        #pragma unroll
        for (int nf = 0; nf < 4; nf++)
            #pragma unroll
            for (int r = 0; r < 4; r++) acc[mf][nf][r] = 0.f;

    const unsigned short* gAh = g_fth + (long long)(m0 + lrow) * KFC + lks;
    const unsigned short* gAl = g_ftl + (long long)(m0 + lrow) * KFC + lks;
    const unsigned short* gBh = g_fcWh + (long long)(n0 + lrow) * KFC + lks;
    const unsigned short* gBl = g_fcWl + (long long)(n0 + lrow) * KFC + lks;
    const int sOff = lrow * FCSTR + lks;

    #define FC_LOAD(st, k0) do {                                   \
        unsigned short* base = sm + (st) * FCSTAGE_SH;             \
        cp16(base +        sOff, gAh + (k0));                      \
        cp16(base + 3072 + sOff, gAl + (k0));                      \
        cp16(base + 6144 + sOff, gBh + (k0));                      \
        cp16(base + 9216 + sOff, gBl + (k0));                      \
    } while (0)

    FC_LOAD(0, 0);
    asm volatile("cp.async.commit_group;");
    FC_LOAD(1, 16);
    asm volatile("cp.async.commit_group;");

    for (int ch = 0; ch < 40; ch++) {
        asm volatile("cp.async.wait_group 1;" ::: "memory");
        __syncthreads();
        if (ch + 2 < 40) FC_LOAD((ch + 2) % 3, (ch + 2) * 16);
        asm volatile("cp.async.commit_group;");

        const unsigned short* base = sm + (ch % 3) * FCSTAGE_SH;
        const unsigned short* Ah = base;
        const unsigned short* Al = base + 3072;
        const unsigned short* Bh = base + 6144;
        const unsigned short* Bl = base + 9216;

        unsigned bh[4][2], bl[4][2];
        ldsm4(bh[0][0], bh[0][1], bh[1][0], bh[1][1], Bh + bpos);
        ldsm4(bh[2][0], bh[2][1], bh[3][0], bh[3][1], Bh + bpos + 16 * FCSTR);
        ldsm4(bl[0][0], bl[0][1], bl[1][0], bl[1][1], Bl + bpos);
        ldsm4(bl[2][0], bl[2][1], bl[3][0], bl[3][1], Bl + bpos + 16 * FCSTR);

        #pragma unroll
        for (int mf = 0; mf < 4; mf++) {
            unsigned ah0, ah1, ah2, ah3, al0, al1, al2, al3;
            ldsm4(ah0, ah1, ah2, ah3, Ah + apos + mf * 16 * FCSTR);
            ldsm4(al0, al1, al2, al3, Al + apos + mf * 16 * FCSTR);
            #pragma unroll
            for (int nf = 0; nf < 4; nf++) {
                mma_bf16(acc[mf][nf], ah0, ah1, ah2, ah3, bh[nf][0], bh[nf][1]);
                mma_bf16(acc[mf][nf], ah0, ah1, ah2, ah3, bl[nf][0], bl[nf][1]);
                mma_bf16(acc[mf][nf], al0, al1, al2, al3, bh[nf][0], bh[nf][1]);
            }
        }
    }
    #undef FC_LOAD

    #pragma unroll
    for (int nf = 0; nf < 4; nf++) {
        const int col = n0 + nbase + nf * 8 + t4 * 2;
        const float2 bias = *(const float2*)&fcb[col];
        #pragma unroll
        for (int mf = 0; mf < 4; mf++) {
            const int r0 = m0 + mbase + mf * 16 + g;
            float2 v0, v1;
            v0.x = acc[mf][nf][0] + bias.x;  v0.y = acc[mf][nf][1] + bias.y;
            v1.x = acc[mf][nf][2] + bias.x;  v1.y = acc[mf][nf][3] + bias.y;
            *(float2*)&out[(long long)r0 * VV + col]       = v0;
            *(float2*)&out[(long long)(r0 + 8) * VV + col] = v1;
        }
    }
}

// ---------------- launch ----------------------------------------------------
extern "C" void kernel_launch(void* const* d_in, const int* in_sizes, int n_in,
                              void* d_out, int out_size) {
    (void)in_sizes; (void)n_in; (void)out_size;
    const float* features = (const float*)d_in[0];
    const int*   captions = (const int*)  d_in[1];
    const float* embed    = (const float*)d_in[2];
    const float* WihS     = (const float*)d_in[3];
    const float* WhhS     = (const float*)d_in[4];
    const float* bihS     = (const float*)d_in[5];
    const float* bhhS     = (const float*)d_in[6];
    const float* WihU     = (const float*)d_in[7];
    const float* WhhU     = (const float*)d_in[8];
    const float* bihU     = (const float*)d_in[9];
    const float* bhhU     = (const float*)d_in[10];
    const float* fcW      = (const float*)d_in[11];
    const float* fcb      = (const float*)d_in[12];
    const float* szW      = (const float*)d_in[13];
    const float* szb      = (const float*)d_in[14];
    const float* wuW      = (const float*)d_in[15];
    const float* wub      = (const float*)d_in[16];
    float* out = (float*)d_out;

    const int fc_smem = 3 * FCSTAGE_SH * (int)sizeof(unsigned short);  // 72KB
    cudaFuncSetAttribute(fc_kernel, cudaFuncAttributeMaxDynamicSharedMemorySize, fc_smem);

    pack_kernel<<<2048, 256>>>(WihS, WhhS, bihS, bhhS, WihU, WhhU, bihU, bhhU, fcW);
    init_kernel<<<BB, 256>>>(features, embed, szW, szb);
    steps_kernel<<<NBS, 128>>>(captions, embed, wuW, wub);
    fc_kernel<<<dim3(12, 250), 256, fc_smem>>>(fcb, out);
}

// round 10
// speedup vs baseline: 1.1836x; 1.1836x over previous
#include <cuda_runtime.h>
#include <cuda_bf16.h>
#include <math.h>

// Problem constants
#define VV    32000
#define EE    256
#define DD    25
#define BB    64
#define TT    24
#define HH    625          // D*D
#define INDIM 906          // E + H + D
#define KTOT  1556         // IN + H(hS) + D(hU)
#define KP    1600         // padded K for gate GEMM (100 k16-tiles)
#define NG    2600         // 4H + 4D real gate rows
#define NGP   2624         // padded to 82*32 (328 n8-tiles)
#define NSTEPS 23
#define KFC   640          // padded 625 for final GEMM
#define NBS   82           // persistent blocks for steps (82 n32-tiles)
#define NKT   100          // KP/16

// ---------------- static device scratch (zero-initialized at load) ----------
// Fragment-major packed gate weights: u32 idx = ((nt*NKT+kt)*2 + j)*32 + lane,
// lane = (n&7)*4 + ((k>>1)&3), j = (k>>3)&1 within k16 tile. Each fragment's
// 32 lanes are one contiguous 128B line.
__device__ __align__(128) unsigned g_WhP[NGP * KP / 2];
__device__ __align__(128) unsigned g_WlP[NGP * KP / 2];
__device__ float g_bias[NG];
__device__ unsigned short g_fcWh[VV * KFC];   // fcW bf16 hi (row-major)
__device__ unsigned short g_fcWl[VV * KFC];   // fcW bf16 lo
// Fragment-major packed xh (A operand, M=64 x K=1600):
// u16 idx = (((m>>4)*NKT + (k>>4))*4 + ((k>>3)&1)*2 + ((m>>3)&1))*64
//           + ((m&7)*4 + ((k>>1)&3))*2 + (k&1)
__device__ __align__(128) unsigned short g_xhhP[BB * KP];
__device__ __align__(128) unsigned short g_xhlP[BB * KP];
__device__ float g_G[BB * NGP];               // gate pre-activations
__device__ float g_cS[BB * HH];
__device__ float g_cU[BB * DD];
__device__ unsigned short g_fth[TT * BB * KFC];  // ft bf16 hi (t=0 + pad stay 0)
__device__ unsigned short g_ftl[TT * BB * KFC];  // ft bf16 lo
__device__ unsigned int g_bar;

__device__ __forceinline__ float sigmoidf_(float x) {
    return __fdividef(1.f, 1.f + __expf(-x));
}
__device__ __forceinline__ float tanhf_(float x) {
    return 1.f - __fdividef(2.f, 1.f + __expf(2.f * x));
}

__device__ __forceinline__ unsigned short f2bf(float v) {
    __nv_bfloat16 b = __float2bfloat16(v);
    return *reinterpret_cast<unsigned short*>(&b);
}
__device__ __forceinline__ float bf2f(unsigned short u) {
    __nv_bfloat16 b;
    *reinterpret_cast<unsigned short*>(&b) = u;
    return __bfloat162float(b);
}

__device__ __forceinline__ int xh_pidx(int m, int k) {
    return (((m >> 4) * NKT + (k >> 4)) * 4 + ((k >> 3) & 1) * 2 + ((m >> 3) & 1)) * 64
           + ((m & 7) * 4 + ((k >> 1) & 3)) * 2 + (k & 1);
}
__device__ __forceinline__ void wr_xh(int b, int idx, float v) {
    unsigned short h = f2bf(v);
    int p = xh_pidx(b, idx);
    g_xhhP[p] = h;
    g_xhlP[p] = f2bf(v - bf2f(h));
}

__device__ __forceinline__ void grid_sync_() {
    __syncthreads();
    if (threadIdx.x == 0) {
        __threadfence();
        unsigned int t = atomicAdd(&g_bar, 1u);
        unsigned int target = t - (t % NBS) + NBS;
        volatile unsigned int* p = &g_bar;
        while ((int)(*p - target) < 0) { }
    }
    __syncthreads();
}

__device__ __forceinline__ void cp16(void* sdst, const void* gsrc) {
    unsigned saddr = (unsigned)__cvta_generic_to_shared(sdst);
    asm volatile("cp.async.cg.shared.global [%0], [%1], 16;" :: "r"(saddr), "l"(gsrc));
}

__device__ __forceinline__ void mma_bf16(float c[4], unsigned a0, unsigned a1,
                                         unsigned a2, unsigned a3,
                                         unsigned b0, unsigned b1) {
    asm volatile(
        "mma.sync.aligned.m16n8k16.row.col.f32.bf16.bf16.f32 "
        "{%0,%1,%2,%3},{%4,%5,%6,%7},{%8,%9},{%0,%1,%2,%3};"
        : "+f"(c[0]), "+f"(c[1]), "+f"(c[2]), "+f"(c[3])
        : "r"(a0), "r"(a1), "r"(a2), "r"(a3), "r"(b0), "r"(b1));
}

__device__ __forceinline__ void ldsm4(unsigned& r0, unsigned& r1, unsigned& r2,
                                      unsigned& r3, const unsigned short* p) {
    unsigned a = (unsigned)__cvta_generic_to_shared(p);
    asm volatile("ldmatrix.sync.aligned.m8n8.x4.shared.b16 {%0,%1,%2,%3},[%4];"
                 : "=r"(r0), "=r"(r1), "=r"(r2), "=r"(r3) : "r"(a));
}

// ---------------- weight packing -------------------------------------------
__device__ __forceinline__ float wcat_val(int n, int k,
                                          const float* WihS, const float* WhhS,
                                          const float* WihU, const float* WhhU) {
    if (n < 4 * HH) {
        if (k < INDIM)           return WihS[n * INDIM + k];
        if (k < INDIM + HH)      return WhhS[n * HH + (k - INDIM)];
        return 0.f;
    } else if (n < NG) {
        int nu = n - 4 * HH;
        if (k < INDIM)                        return WihU[nu * INDIM + k];
        if (k >= INDIM + HH && k < KTOT)      return WhhU[nu * DD + (k - INDIM - HH)];
        return 0.f;
    }
    return 0.f;
}

__global__ void pack_kernel(const float* __restrict__ WihS, const float* __restrict__ WhhS,
                            const float* __restrict__ bihS, const float* __restrict__ bhhS,
                            const float* __restrict__ WihU, const float* __restrict__ WhhU,
                            const float* __restrict__ bihU, const float* __restrict__ bhhU,
                            const float* __restrict__ fcW) {
    const long long n_wU  = (long long)NGP * KP / 2;   // packed u32 count
    const long long n_fc  = (long long)VV * KFC;
    const long long total = n_wU + n_fc + NG;
    for (long long i = blockIdx.x * (long long)blockDim.x + threadIdx.x; i < total;
         i += (long long)gridDim.x * blockDim.x) {
        if (i < n_wU) {
            int lane = (int)(i & 31);
            int j    = (int)((i >> 5) & 1);
            int t    = (int)(i >> 6);
            int kt   = t % NKT, nt = t / NKT;
            int n    = nt * 8 + (lane >> 2);
            int k0   = kt * 16 + j * 8 + (lane & 3) * 2;
            float v0 = wcat_val(n, k0,     WihS, WhhS, WihU, WhhU);
            float v1 = wcat_val(n, k0 + 1, WihS, WhhS, WihU, WhhU);
            unsigned short h0 = f2bf(v0), h1 = f2bf(v1);
            g_WhP[i] = (unsigned)h0 | ((unsigned)h1 << 16);
            unsigned short l0 = f2bf(v0 - bf2f(h0)), l1 = f2bf(v1 - bf2f(h1));
            g_WlP[i] = (unsigned)l0 | ((unsigned)l1 << 16);
        } else if (i < n_wU + n_fc) {
            long long jdx = i - n_wU;
            int k = (int)(jdx % KFC);
            int n = (int)(jdx / KFC);
            float v = (k < HH) ? fcW[(long long)n * HH + k] : 0.f;
            unsigned short h = f2bf(v);
            g_fcWh[jdx] = h;
            g_fcWl[jdx] = f2bf(v - bf2f(h));
        } else {
            int n = (int)(i - n_wU - n_fc);
            g_bias[n] = (n < 4 * HH) ? (bihS[n] + bhhS[n]) : (bihU[n - 4 * HH] + bhhU[n - 4 * HH]);
        }
    }
}

// ---------------- initial state --------------------------------------------
__global__ void init_kernel(const float* __restrict__ features, const float* __restrict__ embed,
                            const float* __restrict__ szW, const float* __restrict__ szb) {
    __shared__ float sf[EE];
    const int b = blockIdx.x, tid = threadIdx.x;
    sf[tid] = features[b * EE + tid];
    __syncthreads();
    for (int c = tid; c < HH; c += 256) {
        float acc = szb[c];
        const float* w = szW + c * EE;
        #pragma unroll 8
        for (int k = 0; k < EE; k++) acc += sf[k] * w[k];
        g_cS[b * HH + c] = acc;
        wr_xh(b, 281 + c, acc);   // cS slot
        wr_xh(b, 906 + c, 0.f);   // hS = 0
    }
    if (tid < DD) {
        g_cU[b * DD + tid] = 0.f;
        wr_xh(b, tid, 0.f);          // cU = 0
        wr_xh(b, 1531 + tid, 0.f);   // hU = 0
    }
    wr_xh(b, 25 + tid, embed[tid]);  // word0
}

// ---------------- persistent recurrence ------------------------------------
// 82 blocks x 128 threads. Phase A: G = xh @ Wcat^T on tensor cores, R7
// structure (4 warps = k-split 4, K=400 each, smem reduction) but fragments
// gathered from fragment-major packed arrays -> every LDG.32 is one 128B line
// (1 wavefront, coalesced). Phase B: blocks 0..63 apply LSTM cells per batch,
// rebuild packed xh, compute ft.
__global__ void __launch_bounds__(128)
steps_kernel(const int* __restrict__ captions, const float* __restrict__ embed,
             const float* __restrict__ wuW, const float* __restrict__ wub) {
    __shared__ float sred[4][2048];
    __shared__ float shS[HH];
    __shared__ float shU[DD];
    __shared__ float sut[HH];

    const int tid  = threadIdx.x;
    const int lane = tid & 31;
    const int w    = tid >> 5;       // warp = k-split index
    const int g    = lane >> 2;
    const int t4   = lane & 3;
    const int n0   = blockIdx.x * 32;
    const int nt0  = blockIdx.x * 4; // first n8-tile of this block

    const unsigned* pAh = (const unsigned*)g_xhhP;
    const unsigned* pAl = (const unsigned*)g_xhlP;

    for (int s = 0; s < NSTEPS; s++) {
        // ---------- phase A: tensor-core gate GEMM, packed fragment gather ----------
        float acc[4][4][4];
        #pragma unroll
        for (int mf = 0; mf < 4; mf++)
            #pragma unroll
            for (int nf = 0; nf < 4; nf++)
                #pragma unroll
                for (int r = 0; r < 4; r++) acc[mf][nf][r] = 0.f;

        for (int it = 0; it < 25; it++) {
            const int kt = w * 25 + it;
            unsigned ah[4][4], al[4][4];
            #pragma unroll
            for (int mf = 0; mf < 4; mf++) {
                const unsigned* pa = pAh + ((mf * NKT + kt) * 4) * 32 + lane;
                const unsigned* pl = pAl + ((mf * NKT + kt) * 4) * 32 + lane;
                ah[mf][0] = __ldcg(pa);      ah[mf][1] = __ldcg(pa + 32);
                ah[mf][2] = __ldcg(pa + 64); ah[mf][3] = __ldcg(pa + 96);
                al[mf][0] = __ldcg(pl);      al[mf][1] = __ldcg(pl + 32);
                al[mf][2] = __ldcg(pl + 64); al[mf][3] = __ldcg(pl + 96);
            }
            unsigned bh[4][2], bl[4][2];
            #pragma unroll
            for (int nf = 0; nf < 4; nf++) {
                const unsigned* pb = g_WhP + (((nt0 + nf) * NKT + kt) * 2) * 32 + lane;
                const unsigned* pc = g_WlP + (((nt0 + nf) * NKT + kt) * 2) * 32 + lane;
                bh[nf][0] = pb[0]; bh[nf][1] = pb[32];
                bl[nf][0] = pc[0]; bl[nf][1] = pc[32];
            }
            #pragma unroll
            for (int mf = 0; mf < 4; mf++)
                #pragma unroll
                for (int nf = 0; nf < 4; nf++) {
                    mma_bf16(acc[mf][nf], ah[mf][0], ah[mf][1], ah[mf][2], ah[mf][3], bh[nf][0], bh[nf][1]);
                    mma_bf16(acc[mf][nf], ah[mf][0], ah[mf][1], ah[mf][2], ah[mf][3], bl[nf][0], bl[nf][1]);
                    mma_bf16(acc[mf][nf], al[mf][0], al[mf][1], al[mf][2], al[mf][3], bh[nf][0], bh[nf][1]);
                }
        }
        // in-block k-split reduction
        #pragma unroll
        for (int mf = 0; mf < 4; mf++)
            #pragma unroll
            for (int nf = 0; nf < 4; nf++)
                #pragma unroll
                for (int r = 0; r < 4; r++) {
                    int m  = mf * 16 + g + ((r >> 1) << 3);
                    int nl = nf * 8 + 2 * t4 + (r & 1);
                    sred[w][m * 32 + nl] = acc[mf][nf][r];
                }
        __syncthreads();
        #pragma unroll
        for (int e4 = 0; e4 < 4; e4++) {
            int e = tid * 4 + e4 * 512;
            float4 v0 = *(float4*)&sred[0][e];
            float4 v1 = *(float4*)&sred[1][e];
            float4 v2 = *(float4*)&sred[2][e];
            float4 v3 = *(float4*)&sred[3][e];
            float4 sOut;
            sOut.x = v0.x + v1.x + v2.x + v3.x;
            sOut.y = v0.y + v1.y + v2.y + v3.y;
            sOut.z = v0.z + v1.z + v2.z + v3.z;
            sOut.w = v0.w + v1.w + v2.w + v3.w;
            int m = e >> 5, nl = e & 31;
            *(float4*)&g_G[m * NGP + n0 + nl] = sOut;
        }
        grid_sync_();

        // ---------- phase B ----------
        if (blockIdx.x < BB) {
            const int b = blockIdx.x;
            const float* p = g_G + b * NGP;
            for (int e = tid; e < HH; e += 128) {
                float gi = __ldcg(p + e)        + g_bias[e];
                float gf = __ldcg(p + HH + e)   + g_bias[HH + e];
                float gg = __ldcg(p + 2*HH + e) + g_bias[2*HH + e];
                float go = __ldcg(p + 3*HH + e) + g_bias[3*HH + e];
                float c = sigmoidf_(gf) * g_cS[b * HH + e] + sigmoidf_(gi) * tanhf_(gg);
                float h = sigmoidf_(go) * tanhf_(c);
                g_cS[b * HH + e] = c;
                shS[e] = h;
                wr_xh(b, 281 + e, c);   // cS for next step
                wr_xh(b, 906 + e, h);   // hS
            }
            if (tid < DD) {
                const int e = tid, u = 4 * HH;
                float gi = __ldcg(p + u + e)      + g_bias[u + e];
                float gf = __ldcg(p + u + 25 + e) + g_bias[u + 25 + e];
                float gg = __ldcg(p + u + 50 + e) + g_bias[u + 50 + e];
                float go = __ldcg(p + u + 75 + e) + g_bias[u + 75 + e];
                float c = sigmoidf_(gf) * g_cU[b * DD + e] + sigmoidf_(gi) * tanhf_(gg);
                float h = sigmoidf_(go) * tanhf_(c);
                g_cU[b * DD + e] = c;
                shU[e] = h;
                wr_xh(b, e, c);          // cU
                wr_xh(b, 1531 + e, h);   // hU
            }
            if (s + 1 < NSTEPS) {
                const int wd = captions[b * TT + (s + 1)];
                for (int e = tid; e < EE; e += 128) wr_xh(b, 25 + e, embed[wd * EE + e]);
            }
            __syncthreads();
            for (int pp = tid; pp < HH; pp += 128) {   // ut = hU @ wuW.T + wub
                float acc2 = wub[pp];
                const float* r = wuW + pp * DD;
                #pragma unroll
                for (int d2 = 0; d2 < DD; d2++) acc2 += shU[d2] * r[d2];
                sut[pp] = acc2;
            }
            __syncthreads();
            const long long base = (long long)((s + 1) * BB + b) * KFC;
            for (int idx = tid; idx < HH; idx += 128) {  // ft = ut @ m2
                int i2 = idx / DD, j2 = idx - i2 * DD;
                float acc2 = 0.f;
                #pragma unroll
                for (int k2 = 0; k2 < DD; k2++) acc2 += sut[i2 * DD + k2] * shS[k2 * DD + j2];
                unsigned short h = f2bf(acc2);
                g_fth[base + idx] = h;
                g_ftl[base + idx] = f2bf(acc2 - bf2f(h));
            }
        }
        grid_sync_();
    }
}

// ---------------- final projection on tensor cores --------------------------
// (unchanged from R8: 537us measured) bf16 hi/lo 3-term mma, ldmatrix loads,
// 3-stage cp.async pipeline, grid m-fastest so fcW streams from DRAM ~once.
#define FCSTR 24   // smem row stride in bf16
#define FCSTAGE_SH 12288   // shorts per stage (4 arrays x 128*24)
__global__ void __launch_bounds__(256, 2)
fc_kernel(const float* __restrict__ fcb, float* __restrict__ out) {
    extern __shared__ unsigned short sm[];

    const int tid   = threadIdx.x;
    const int lane  = tid & 31;
    const int wid   = tid >> 5;
    const int g     = lane >> 2;
    const int t4    = lane & 3;
    const int mbase = (wid & 1) * 64;
    const int nbase = (wid >> 1) * 32;
    const int m0    = blockIdx.x * 128;   // m fastest
    const int n0    = blockIdx.y * 128;

    const int lrow  = tid >> 1;
    const int lks   = (tid & 1) * 8;

    const int apos = (mbase + (lane & 15)) * FCSTR + (lane >> 4) * 8;
    const int bpos = (nbase + ((lane >> 4) & 1) * 8 + (lane & 7)) * FCSTR + ((lane >> 3) & 1) * 8;

    float acc[4][4][4];
    #pragma unroll
    for (int mf = 0; mf < 4; mf++)
        #pragma unroll
        for (int nf = 0; nf < 4; nf++)
            #pragma unroll
            for (int r = 0; r < 4; r++) acc[mf][nf][r] = 0.f;

    const unsigned short* gAh = g_fth + (long long)(m0 + lrow) * KFC + lks;
    const unsigned short* gAl = g_ftl + (long long)(m0 + lrow) * KFC + lks;
    const unsigned short* gBh = g_fcWh + (long long)(n0 + lrow) * KFC + lks;
    const unsigned short* gBl = g_fcWl + (long long)(n0 + lrow) * KFC + lks;
    const int sOff = lrow * FCSTR + lks;

    #define FC_LOAD(st, k0) do {                                   \
        unsigned short* base = sm + (st) * FCSTAGE_SH;             \
        cp16(base +        sOff, gAh + (k0));                      \
        cp16(base + 3072 + sOff, gAl + (k0));                      \
        cp16(base + 6144 + sOff, gBh + (k0));                      \
        cp16(base + 9216 + sOff, gBl + (k0));                      \
    } while (0)

    FC_LOAD(0, 0);
    asm volatile("cp.async.commit_group;");
    FC_LOAD(1, 16);
    asm volatile("cp.async.commit_group;");

    for (int ch = 0; ch < 40; ch++) {
        asm volatile("cp.async.wait_group 1;" ::: "memory");
        __syncthreads();
        if (ch + 2 < 40) FC_LOAD((ch + 2) % 3, (ch + 2) * 16);
        asm volatile("cp.async.commit_group;");

        const unsigned short* base = sm + (ch % 3) * FCSTAGE_SH;
        const unsigned short* Ah = base;
        const unsigned short* Al = base + 3072;
        const unsigned short* Bh = base + 6144;
        const unsigned short* Bl = base + 9216;

        unsigned bh[4][2], bl[4][2];
        ldsm4(bh[0][0], bh[0][1], bh[1][0], bh[1][1], Bh + bpos);
        ldsm4(bh[2][0], bh[2][1], bh[3][0], bh[3][1], Bh + bpos + 16 * FCSTR);
        ldsm4(bl[0][0], bl[0][1], bl[1][0], bl[1][1], Bl + bpos);
        ldsm4(bl[2][0], bl[2][1], bl[3][0], bl[3][1], Bl + bpos + 16 * FCSTR);

        #pragma unroll
        for (int mf = 0; mf < 4; mf++) {
            unsigned ah0, ah1, ah2, ah3, al0, al1, al2, al3;
            ldsm4(ah0, ah1, ah2, ah3, Ah + apos + mf * 16 * FCSTR);
            ldsm4(al0, al1, al2, al3, Al + apos + mf * 16 * FCSTR);
            #pragma unroll
            for (int nf = 0; nf < 4; nf++) {
                mma_bf16(acc[mf][nf], ah0, ah1, ah2, ah3, bh[nf][0], bh[nf][1]);
                mma_bf16(acc[mf][nf], ah0, ah1, ah2, ah3, bl[nf][0], bl[nf][1]);
                mma_bf16(acc[mf][nf], al0, al1, al2, al3, bh[nf][0], bh[nf][1]);
            }
        }
    }
    #undef FC_LOAD

    #pragma unroll
    for (int nf = 0; nf < 4; nf++) {
        const int col = n0 + nbase + nf * 8 + t4 * 2;
        const float2 bias = *(const float2*)&fcb[col];
        #pragma unroll
        for (int mf = 0; mf < 4; mf++) {
            const int r0 = m0 + mbase + mf * 16 + g;
            float2 v0, v1;
            v0.x = acc[mf][nf][0] + bias.x;  v0.y = acc[mf][nf][1] + bias.y;
            v1.x = acc[mf][nf][2] + bias.x;  v1.y = acc[mf][nf][3] + bias.y;
            *(float2*)&out[(long long)r0 * VV + col]       = v0;
            *(float2*)&out[(long long)(r0 + 8) * VV + col] = v1;
        }
    }
}

// ---------------- launch ----------------------------------------------------
extern "C" void kernel_launch(void* const* d_in, const int* in_sizes, int n_in,
                              void* d_out, int out_size) {
    (void)in_sizes; (void)n_in; (void)out_size;
    const float* features = (const float*)d_in[0];
    const int*   captions = (const int*)  d_in[1];
    const float* embed    = (const float*)d_in[2];
    const float* WihS     = (const float*)d_in[3];
    const float* WhhS     = (const float*)d_in[4];
    const float* bihS     = (const float*)d_in[5];
    const float* bhhS     = (const float*)d_in[6];
    const float* WihU     = (const float*)d_in[7];
    const float* WhhU     = (const float*)d_in[8];
    const float* bihU     = (const float*)d_in[9];
    const float* bhhU     = (const float*)d_in[10];
    const float* fcW      = (const float*)d_in[11];
    const float* fcb      = (const float*)d_in[12];
    const float* szW      = (const float*)d_in[13];
    const float* szb      = (const float*)d_in[14];
    const float* wuW      = (const float*)d_in[15];
    const float* wub      = (const float*)d_in[16];
    float* out = (float*)d_out;

    const int fc_smem = 3 * FCSTAGE_SH * (int)sizeof(unsigned short);  // 72KB
    cudaFuncSetAttribute(fc_kernel, cudaFuncAttributeMaxDynamicSharedMemorySize, fc_smem);

    pack_kernel<<<2048, 256>>>(WihS, WhhS, bihS, bhhS, WihU, WhhU, bihU, bhhU, fcW);
    init_kernel<<<BB, 256>>>(features, embed, szW, szb);
    steps_kernel<<<NBS, 128>>>(captions, embed, wuW, wub);
    fc_kernel<<<dim3(12, 250), 256, fc_smem>>>(fcb, out);
}